// round 6
// baseline (speedup 1.0000x reference)
#include <cuda_runtime.h>
#include <math_constants.h>

// Problem constants
#define TAU_SYN_INV 0.5f
#define TAU_MEM_INV 0.5f
#define V_TH        1.0f
#define V_RESET     0.0f
#define INHIB      (-5.0f)

constexpr int N_COLS  = 8192;
constexpr int THREADS = 512;
constexpr int NVEC    = N_COLS / 4;            // 2048 float4 per row
constexpr int ITERS   = NVEC / THREADS;        // 4 float4 per thread
constexpr int NWARPS  = THREADS / 32;          // 16

// (val, idx) argmax with first-index tie-break: prefer larger val, then smaller idx.
__device__ __forceinline__ void amax_update(float& bv, int& bi, float v, int i) {
    if (v > bv || (v == bv && i < bi)) { bv = v; bi = i; }
}

__global__ __launch_bounds__(THREADS, 2)
void lif_wta_kernel(const float4* __restrict__ x,
                    const float4* __restrict__ vmem,
                    const float4* __restrict__ isyn,
                    float4* __restrict__ z_out,
                    float4* __restrict__ v_out,
                    float4* __restrict__ i_out)
{
    const int row  = blockIdx.x;
    const size_t base = (size_t)row * NVEC;
    const int tid  = threadIdx.x;

    __shared__ float s_wval[NWARPS];
    __shared__ int   s_widx[NWARPS];
    __shared__ float s_best;
    __shared__ int   s_bidx;

    float4 vn[ITERS];                 // stash v_new in registers for the (rare) no-spike case
    float best = -CUDART_INF_F;
    int   bidx = N_COLS;              // sentinel larger than any valid index

    // ---- Phase 1: compute, stream z and i_new, stash v_new, local argmax ----
    // All global traffic is touch-once: use streaming (evict-first) hints.
    #pragma unroll
    for (int it = 0; it < ITERS; it++) {
        const int c = tid + it * THREADS;
        const float4 xv = __ldcs(&x[base + c]);
        const float4 vv = __ldcs(&vmem[base + c]);
        const float4 iv = __ldcs(&isyn[base + c]);

        float4 in4, vn4, z4;
        const float* xp = (const float*)&xv;
        const float* vp = (const float*)&vv;
        const float* ip = (const float*)&iv;
        float* inp = (float*)&in4;
        float* vnp = (float*)&vn4;
        float* zp  = (float*)&z4;

        #pragma unroll
        for (int j = 0; j < 4; j++) {
            const float i_new = ip[j] + TAU_SYN_INV * (xp[j] - ip[j]);
            const float v_new = vp[j] + TAU_MEM_INV * (i_new - vp[j]);
            const bool  spike = (v_new >= V_TH);
            inp[j] = i_new;
            vnp[j] = v_new;
            zp[j]  = spike ? 1.0f : 0.0f;
            if (spike) amax_update(best, bidx, v_new, c * 4 + j);
        }
        __stcs(&i_out[base + c], in4);
        __stcs(&z_out[base + c], z4);
        vn[it] = vn4;
    }

    // ---- Warp reduction ----
    #pragma unroll
    for (int off = 16; off > 0; off >>= 1) {
        const float ov = __shfl_down_sync(0xFFFFFFFFu, best, off);
        const int   oi = __shfl_down_sync(0xFFFFFFFFu, bidx, off);
        amax_update(best, bidx, ov, oi);
    }
    if ((tid & 31) == 0) {
        s_wval[tid >> 5] = best;
        s_widx[tid >> 5] = bidx;
    }
    __syncthreads();

    // ---- Final reduction in warp 0 ----
    if (tid < 32) {
        float fb = (tid < NWARPS) ? s_wval[tid] : -CUDART_INF_F;
        int   fi = (tid < NWARPS) ? s_widx[tid] : N_COLS;
        #pragma unroll
        for (int off = 16; off > 0; off >>= 1) {
            const float ov = __shfl_down_sync(0xFFFFFFFFu, fb, off);
            const int   oi = __shfl_down_sync(0xFFFFFFFFu, fi, off);
            amax_update(fb, fi, ov, oi);
        }
        if (tid == 0) { s_best = fb; s_bidx = fi; }
    }
    __syncthreads();

    const bool any_spike = (s_best > -CUDART_INF_F);   // block-uniform
    const int  winner    = s_bidx;

    // ---- Phase 2: write v_out ----
    #pragma unroll
    for (int it = 0; it < ITERS; it++) {
        const int c = tid + it * THREADS;
        float4 o;
        if (any_spike) {
            o.x = INHIB; o.y = INHIB; o.z = INHIB; o.w = INHIB;
            const int b4 = c * 4;
            if (winner >= b4 && winner < b4 + 4) {
                ((float*)&o)[winner - b4] = V_RESET;   // winner spiked -> v_after = V_RESET
            }
        } else {
            o = vn[it];                                // no spikes: v_out = v_new unchanged
        }
        __stcs(&v_out[base + c], o);
    }
}

extern "C" void kernel_launch(void* const* d_in, const int* in_sizes, int n_in,
                              void* d_out, int out_size) {
    const float4* x = (const float4*)d_in[0];
    const float4* v = (const float4*)d_in[1];
    const float4* i = (const float4*)d_in[2];

    const long long total = in_sizes[0];          // B * N
    const int B = (int)(total / N_COLS);
    const long long bn = (long long)B * N_COLS;

    float* out = (float*)d_out;
    float4* z_out = (float4*)(out);               // outputs in reference order: z, v_out, i_new
    float4* v_out = (float4*)(out + bn);
    float4* i_out = (float4*)(out + 2 * bn);

    lif_wta_kernel<<<B, THREADS>>>(x, v, i, z_out, v_out, i_out);
}

// round 8
// speedup vs baseline: 1.0239x; 1.0239x over previous
#include <cuda_runtime.h>
#include <math_constants.h>

// Problem constants
#define TAU_SYN_INV 0.5f
#define TAU_MEM_INV 0.5f
#define V_TH        1.0f
#define V_RESET     0.0f
#define INHIB      (-5.0f)

constexpr int N_COLS  = 8192;
constexpr int THREADS = 512;
constexpr int NVEC    = N_COLS / 4;            // 2048 float4 per row
constexpr int ITERS   = NVEC / THREADS;        // 4 float4 per thread
constexpr int NWARPS  = THREADS / 32;          // 16

// (val, idx) argmax with first-index tie-break: prefer larger val, then smaller idx.
__device__ __forceinline__ void amax_update(float& bv, int& bi, float v, int i) {
    if (v > bv || (v == bv && i < bi)) { bv = v; bi = i; }
}

__global__ __launch_bounds__(THREADS, 2)
void lif_wta_kernel(const float4* __restrict__ x,
                    const float4* __restrict__ vmem,
                    const float4* __restrict__ isyn,
                    float4* __restrict__ z_out,
                    float4* __restrict__ v_out,
                    float4* __restrict__ i_out)
{
    const int row  = blockIdx.x;
    const size_t base = (size_t)row * NVEC;
    const int tid  = threadIdx.x;

    __shared__ float s_wval[NWARPS];
    __shared__ int   s_widx[NWARPS];
    __shared__ float s_best;
    __shared__ int   s_bidx;

    float best = -CUDART_INF_F;
    int   bidx = N_COLS;              // sentinel larger than any valid index

    // ---- Phase 1: compute, stream z and i_new, local argmax ----
    // Nothing computed here needs to live past the barrier: v_new is
    // recomputed in the (probability ~e^-165) no-spike fallback, which frees
    // registers and lets ptxas front-batch the loads (higher MLP).
    #pragma unroll
    for (int it = 0; it < ITERS; it++) {
        const int c = tid + it * THREADS;
        const float4 xv = x[base + c];
        const float4 vv = vmem[base + c];
        const float4 iv = isyn[base + c];

        float4 in4, z4;
        const float* xp = (const float*)&xv;
        const float* vp = (const float*)&vv;
        const float* ip = (const float*)&iv;
        float* inp = (float*)&in4;
        float* zp  = (float*)&z4;

        #pragma unroll
        for (int j = 0; j < 4; j++) {
            const float i_new = ip[j] + TAU_SYN_INV * (xp[j] - ip[j]);
            const float v_new = vp[j] + TAU_MEM_INV * (i_new - vp[j]);
            const bool  spike = (v_new >= V_TH);
            inp[j] = i_new;
            zp[j]  = spike ? 1.0f : 0.0f;
            if (spike) amax_update(best, bidx, v_new, c * 4 + j);
        }
        i_out[base + c] = in4;
        z_out[base + c] = z4;
    }

    // ---- Warp reduction ----
    #pragma unroll
    for (int off = 16; off > 0; off >>= 1) {
        const float ov = __shfl_down_sync(0xFFFFFFFFu, best, off);
        const int   oi = __shfl_down_sync(0xFFFFFFFFu, bidx, off);
        amax_update(best, bidx, ov, oi);
    }
    if ((tid & 31) == 0) {
        s_wval[tid >> 5] = best;
        s_widx[tid >> 5] = bidx;
    }
    __syncthreads();

    // ---- Final reduction in warp 0 ----
    if (tid < 32) {
        float fb = (tid < NWARPS) ? s_wval[tid] : -CUDART_INF_F;
        int   fi = (tid < NWARPS) ? s_widx[tid] : N_COLS;
        #pragma unroll
        for (int off = 16; off > 0; off >>= 1) {
            const float ov = __shfl_down_sync(0xFFFFFFFFu, fb, off);
            const int   oi = __shfl_down_sync(0xFFFFFFFFu, fi, off);
            amax_update(fb, fi, ov, oi);
        }
        if (tid == 0) { s_best = fb; s_bidx = fi; }
    }
    __syncthreads();

    const bool any_spike = (s_best > -CUDART_INF_F);   // block-uniform
    const int  winner    = s_bidx;

    // ---- Phase 2: write v_out ----
    if (any_spike) {
        // Winner-take-all row: winner gets V_RESET (it spiked), rest get INHIB.
        #pragma unroll
        for (int it = 0; it < ITERS; it++) {
            const int c = tid + it * THREADS;
            float4 o;
            o.x = INHIB; o.y = INHIB; o.z = INHIB; o.w = INHIB;
            const int b4 = c * 4;
            if (winner >= b4 && winner < b4 + 4) {
                ((float*)&o)[winner - b4] = V_RESET;
            }
            v_out[base + c] = o;
        }
    } else {
        // No spikes in row (astronomically rare): recompute v_new from inputs
        // (re-reads hit L2; this row's lines were just fetched).
        #pragma unroll
        for (int it = 0; it < ITERS; it++) {
            const int c = tid + it * THREADS;
            const float4 xv = x[base + c];
            const float4 vv = vmem[base + c];
            const float4 iv = isyn[base + c];
            float4 o;
            const float* xp = (const float*)&xv;
            const float* vp = (const float*)&vv;
            const float* ip = (const float*)&iv;
            float* op = (float*)&o;
            #pragma unroll
            for (int j = 0; j < 4; j++) {
                const float i_new = ip[j] + TAU_SYN_INV * (xp[j] - ip[j]);
                op[j] = vp[j] + TAU_MEM_INV * (i_new - vp[j]);
            }
            v_out[base + c] = o;
        }
    }
}

extern "C" void kernel_launch(void* const* d_in, const int* in_sizes, int n_in,
                              void* d_out, int out_size) {
    const float4* x = (const float4*)d_in[0];
    const float4* v = (const float4*)d_in[1];
    const float4* i = (const float4*)d_in[2];

    const long long total = in_sizes[0];          // B * N
    const int B = (int)(total / N_COLS);
    const long long bn = (long long)B * N_COLS;

    float* out = (float*)d_out;
    float4* z_out = (float4*)(out);               // outputs in reference order: z, v_out, i_new
    float4* v_out = (float4*)(out + bn);
    float4* i_out = (float4*)(out + 2 * bn);

    lif_wta_kernel<<<B, THREADS>>>(x, v, i, z_out, v_out, i_out);
}